// round 8
// baseline (speedup 1.0000x reference)
#include <cuda_runtime.h>
#include <cuda_bf16.h>
#include <math.h>
#include <stdint.h>

// Problem constants
#define BATCH 2
#define SEQ   1024
#define DMODEL 1024
#define NHEAD 16
#define HEADD 64
#define NLAYER 3
#define FFDIM 4096
#define VOCAB 32000
#define MROWS (BATCH*SEQ)   // 2048

// weight buffer layout (elems): per layer Wq,Wk,Wv,Wo (4x D*D), W1 (F*D), W2 (D*F)
#define DD (DMODEL*DMODEL)
#define LW (4*DD + 2*DMODEL*FFDIM)          // 12582912
#define WOUT_OFF (NLAYER*LW)                 // 37748736
#define WTOT (WOUT_OFF + DMODEL*VOCAB)       // 70516736

// ---------------- scratch (device globals) -----------------------------------
__device__ float g_h  [MROWS*DMODEL];
__device__ float g_q  [MROWS*DMODEL];
__device__ float g_k  [MROWS*DMODEL];
__device__ float g_v  [MROWS*DMODEL];
__device__ __nv_bfloat16 g_xnh[MROWS*DMODEL];
__device__ __nv_bfloat16 g_xnl[MROWS*DMODEL];
__device__ __nv_bfloat16 g_atth[MROWS*DMODEL];
__device__ __nv_bfloat16 g_attl[MROWS*DMODEL];
__device__ __nv_bfloat16 g_ffh[MROWS*FFDIM];
__device__ __nv_bfloat16 g_ffl[MROWS*FFDIM];
__device__ __nv_bfloat16 g_wth[WTOT];
__device__ __nv_bfloat16 g_wtl[WTOT];
__device__ int   g_x_is64;

// ---------------- helpers -----------------------------------------------------
__device__ __forceinline__ uint32_t smem_u32(const void* p) {
    uint32_t a;
    asm("{ .reg .u64 t; cvta.to.shared.u64 t, %1; cvt.u32.u64 %0, t; }" : "=r"(a) : "l"(p));
    return a;
}
// hi = trunc-to-bf16 pair (packed), lo = rn-bf16(v - hi) pair (packed)
__device__ __forceinline__ void split2(float vx, float vy, uint32_t& hi, uint32_t& lo) {
    uint32_t ux = __float_as_uint(vx);
    uint32_t uy = __float_as_uint(vy);
    hi = __byte_perm(ux, uy, 0x7632);
    float lx = vx - __uint_as_float(ux & 0xFFFF0000u);
    float ly = vy - __uint_as_float(uy & 0xFFFF0000u);
    asm("cvt.rn.bf16x2.f32 %0, %1, %2;" : "=r"(lo) : "f"(ly), "f"(lx));
}
__device__ __forceinline__ void ldsm4(uint32_t* r, uint32_t addr) {
    asm volatile("ldmatrix.sync.aligned.m8n8.x4.shared.b16 {%0,%1,%2,%3}, [%4];"
                 : "=r"(r[0]), "=r"(r[1]), "=r"(r[2]), "=r"(r[3]) : "r"(addr));
}
__device__ __forceinline__ void mma16816(float* c, const uint32_t* a, const uint32_t* b) {
    asm volatile(
        "mma.sync.aligned.m16n8k16.row.col.f32.bf16.bf16.f32 "
        "{%0,%1,%2,%3}, {%4,%5,%6,%7}, {%8,%9}, {%0,%1,%2,%3};"
        : "+f"(c[0]), "+f"(c[1]), "+f"(c[2]), "+f"(c[3])
        : "r"(a[0]), "r"(a[1]), "r"(a[2]), "r"(a[3]), "r"(b[0]), "r"(b[1]));
}
__device__ __forceinline__ void cpa16(uint32_t s, const void* g) {
    asm volatile("cp.async.cg.shared.global [%0], [%1], 16;" :: "r"(s), "l"(g));
}

// ---------------- token dtype detection --------------------------------------
__global__ void detect_kernel(const int* __restrict__ x32, int ntok) {
    __shared__ int ok;
    if (threadIdx.x == 0) ok = 1;
    __syncthreads();
    for (int i = threadIdx.x * 2 + 1; i < ntok; i += 2 * blockDim.x) {
        if (x32[i] != 0) { ok = 0; break; }
    }
    __syncthreads();
    if (threadIdx.x == 0) g_x_is64 = ok;
}

// ---------------- embedding ---------------------------------------------------
__global__ __launch_bounds__(256) void embed_kernel(
    const void* __restrict__ x,
    const float* __restrict__ tok_emb,
    const float* __restrict__ pos_emb)
{
    int row = blockIdx.x;
    int s = row & (SEQ - 1);
    long long t;
    if (g_x_is64) t = ((const long long*)x)[row];
    else          t = (long long)(((const int*)x)[row]);
    const float4* te = (const float4*)(tok_emb + (size_t)t * DMODEL);
    const float4* pe = (const float4*)(pos_emb + (size_t)s * DMODEL);
    float4* out = (float4*)(g_h + (size_t)row * DMODEL);
    int i = threadIdx.x;
    float4 a = te[i], b = pe[i];
    out[i] = make_float4(a.x + b.x, a.y + b.y, a.z + b.z, a.w + b.w);
}

// ---------------- weight transpose + split: W[K,N] -> Wt[N,K] bf16 hi/lo ------
__global__ __launch_bounds__(256) void convw_kernel(
    const float* __restrict__ W, __nv_bfloat16* __restrict__ Th,
    __nv_bfloat16* __restrict__ Tl, int K, int N)
{
    __shared__ float sm[32][33];
    int bk = blockIdx.y * 32, bn = blockIdx.x * 32;
    int t = threadIdx.x;
    int col = t & 31, rq = t >> 5;
    #pragma unroll
    for (int i = 0; i < 4; i++) {
        int k = rq + i * 8;
        sm[k][col] = W[(size_t)(bk + k) * N + bn + col];
    }
    __syncthreads();
    #pragma unroll
    for (int i = 0; i < 4; i++) {
        int n = rq + i * 8;
        int kk = col;
        float v = sm[kk][n];
        uint32_t u = __float_as_uint(v);
        size_t o = (size_t)(bn + n) * K + bk + kk;
        Th[o] = __ushort_as_bfloat16((unsigned short)(u >> 16));
        Tl[o] = __float2bfloat16(v - __uint_as_float(u & 0xFFFF0000u));
    }
}

// ---------------- layernorm -> bf16 hi/lo -------------------------------------
__global__ __launch_bounds__(256) void ln_kernel(
    const float* __restrict__ x, const float* __restrict__ g,
    const float* __restrict__ b,
    __nv_bfloat16* __restrict__ yh, __nv_bfloat16* __restrict__ yl)
{
    int row = blockIdx.x;
    int tid = threadIdx.x;
    float4 val = ((const float4*)(x + (size_t)row * DMODEL))[tid];
    float s = val.x + val.y + val.z + val.w;
    float q = val.x*val.x + val.y*val.y + val.z*val.z + val.w*val.w;
    #pragma unroll
    for (int o = 16; o > 0; o >>= 1) {
        s += __shfl_xor_sync(0xffffffffu, s, o);
        q += __shfl_xor_sync(0xffffffffu, q, o);
    }
    __shared__ float sa[8], sb[8];
    __shared__ float s_mu, s_inv;
    int w = tid >> 5;
    if ((tid & 31) == 0) { sa[w] = s; sb[w] = q; }
    __syncthreads();
    if (tid == 0) {
        float ts = 0.f, tq = 0.f;
        #pragma unroll
        for (int i = 0; i < 8; i++) { ts += sa[i]; tq += sb[i]; }
        float mu = ts * (1.0f / DMODEL);
        float var = tq * (1.0f / DMODEL) - mu * mu;
        s_mu = mu;
        s_inv = rsqrtf(var + 1e-5f);
    }
    __syncthreads();
    float mu = s_mu, inv = s_inv;
    float4 gg = ((const float4*)g)[tid];
    float4 bb = ((const float4*)b)[tid];
    float ox = (val.x - mu) * inv * gg.x + bb.x;
    float oy = (val.y - mu) * inv * gg.y + bb.y;
    float oz = (val.z - mu) * inv * gg.z + bb.z;
    float ow = (val.w - mu) * inv * gg.w + bb.w;
    uint32_t h0, l0, h1, l1;
    split2(ox, oy, h0, l0);
    split2(oz, ow, h1, l1);
    ((uint2*)yh)[row * 256 + tid] = make_uint2(h0, h1);
    ((uint2*)yl)[row * 256 + tid] = make_uint2(l0, l1);
}

// ============================================================================
// bf16 split GEMM, cp.async 4-stage pipeline:
//   C[M,N] = A @ W + bias ;  A,W pre-split hi/lo bf16 (A:[M,K] row, W:[N,K] row)
//   D = AhiBhi + AhiBlo + AloBhi
// Block 128x128, 8 warps (4m x 2n), warp tile 32x64, K-chunk 32.
// ============================================================================
#define ROWB    80
#define TILE_B  10240       // 128 rows * 80B
#define STAGE_B 40960       // Ahi Alo Bhi Blo
#define STAGES  4
#define GEMM_SMEM (STAGES*STAGE_B)   // 163840

__global__ __launch_bounds__(256, 1) void tgemm_kernel(
    int M, int N, int K,
    const __nv_bfloat16* __restrict__ Ahi, const __nv_bfloat16* __restrict__ Alo,
    const __nv_bfloat16* __restrict__ Bhi, const __nv_bfloat16* __restrict__ Blo,
    const float* __restrict__ bias, float* C, int mode,
    __nv_bfloat16* outh, __nv_bfloat16* outl)
{
    extern __shared__ char smem[];
    uint32_t sb = smem_u32(smem);
    int tid = threadIdx.x;
    int wid = tid >> 5;
    int lane = tid & 31;
    int bm = blockIdx.y * 128;
    int bn = blockIdx.x * 128;

    float acc[2][8][4];
    #pragma unroll
    for (int i = 0; i < 2; i++)
        #pragma unroll
        for (int j = 0; j < 8; j++)
            #pragma unroll
            for (int q = 0; q < 4; q++) acc[i][j][q] = 0.f;

    const int KT = K >> 5;

    // per-thread copy sources: threads 0..127 -> A row, 128..255 -> B row
    const char *g0, *g1;
    uint32_t sdst;
    {
        if (tid < 128) {
            g0 = (const char*)(Ahi + (size_t)(bm + tid) * K);
            g1 = (const char*)(Alo + (size_t)(bm + tid) * K);
            sdst = sb + tid * ROWB;                 // Ahi tile; Alo at +TILE_B
        } else {
            int r = tid - 128;
            g0 = (const char*)(Bhi + (size_t)(bn + r) * K);
            g1 = (const char*)(Blo + (size_t)(bn + r) * K);
            sdst = sb + 2 * TILE_B + r * ROWB;      // Bhi tile; Blo at +TILE_B
        }
    }

#define ISSUE_STAGE(slot, kt) do {                                            \
        uint32_t s_ = sdst + (slot) * STAGE_B;                                \
        const char* p0_ = g0 + (size_t)(kt) * 64;                             \
        const char* p1_ = g1 + (size_t)(kt) * 64;                             \
        cpa16(s_,      p0_);      cpa16(s_ + 16,          p0_ + 16);          \
        cpa16(s_ + 32, p0_ + 32); cpa16(s_ + 48,          p0_ + 48);          \
        cpa16(s_ + TILE_B,      p1_);      cpa16(s_ + TILE_B + 16, p1_ + 16); \
        cpa16(s_ + TILE_B + 32, p1_ + 32); cpa16(s_ + TILE_B + 48, p1_ + 48); \
        asm volatile("cp.async.commit_group;" ::: "memory");                  \
    } while (0)

    ISSUE_STAGE(0, 0);
    ISSUE_STAGE(1, 1);
    ISSUE_STAGE(2, 2);

    // fragment lane addressing
    int wm = wid & 3;
    int wn = wid >> 2;
    int g  = lane >> 3;
    int lr = lane & 7;
    uint32_t a_off = (uint32_t)((wm * 32 + (g & 1) * 8 + lr) * ROWB + ((g >> 1) * 8) * 2);
    uint32_t b_off = (uint32_t)((wn * 64 + (g >> 1) * 8 + lr) * ROWB + ((g & 1) * 8) * 2);

    for (int kt = 0; kt < KT; kt++) {
        asm volatile("cp.async.wait_group 2;" ::: "memory");
        __syncthreads();
        if (kt + 3 < KT) ISSUE_STAGE((kt + 3) & 3, kt + 3);

        int slot = kt & 3;
        uint32_t sA = sb + slot * STAGE_B + a_off;
        uint32_t sB = sb + slot * STAGE_B + 2 * TILE_B + b_off;

        #pragma unroll
        for (int ks = 0; ks < 2; ks++) {
            uint32_t ah[2][4], al[2][4];
            uint32_t bh[8][2], bl[8][2];
            #pragma unroll
            for (int mt = 0; mt < 2; mt++) {
                uint32_t addr = sA + mt * 16 * ROWB + ks * 32;
                ldsm4(ah[mt], addr);
                ldsm4(al[mt], addr + TILE_B);
            }
            #pragma unroll
            for (int nt2 = 0; nt2 < 4; nt2++) {
                uint32_t addr = sB + nt2 * 16 * ROWB + ks * 32;
                uint32_t r[4];
                ldsm4(r, addr);
                bh[nt2*2][0] = r[0]; bh[nt2*2][1] = r[1];
                bh[nt2*2+1][0] = r[2]; bh[nt2*2+1][1] = r[3];
                ldsm4(r, addr + TILE_B);
                bl[nt2*2][0] = r[0]; bl[nt2*2][1] = r[1];
                bl[nt2*2+1][0] = r[2]; bl[nt2*2+1][1] = r[3];
            }
            #pragma unroll
            for (int mt = 0; mt < 2; mt++)
                #pragma unroll
                for (int nt = 0; nt < 8; nt++) {
                    mma16816(acc[mt][nt], ah[mt], bh[nt]);
                    mma16816(acc[mt][nt], ah[mt], bl[nt]);
                    mma16816(acc[mt][nt], al[mt], bh[nt]);
                }
        }
        __syncthreads();
    }
#undef ISSUE_STAGE

    // ---- epilogue ----
    int r0 = lane >> 2;
    int cc = (lane & 3) * 2;
    #pragma unroll
    for (int mt = 0; mt < 2; mt++) {
        int m0 = bm + wm * 32 + mt * 16 + r0;
        #pragma unroll
        for (int nt = 0; nt < 8; nt++) {
            int n0 = bn + wn * 64 + nt * 8 + cc;
            float b0 = bias[n0], b1 = bias[n0 + 1];
            #pragma unroll
            for (int half = 0; half < 2; half++) {
                int m = m0 + half * 8;
                float vx = acc[mt][nt][half*2 + 0] + b0;
                float vy = acc[mt][nt][half*2 + 1] + b1;
                if (mode == 1) {
                    vx = 0.5f * vx * (1.0f + erff(vx * 0.70710678118654752f));
                    vy = 0.5f * vy * (1.0f + erff(vy * 0.70710678118654752f));
                    uint32_t h, l;
                    split2(vx, vy, h, l);
                    *(uint32_t*)((char*)outh + ((size_t)m * N + n0) * 2) = h;
                    *(uint32_t*)((char*)outl + ((size_t)m * N + n0) * 2) = l;
                } else {
                    float* cp = C + (size_t)m * N + n0;
                    if (mode == 2) {
                        float2 old = *(float2*)cp;
                        vx += old.x; vy += old.y;
                    }
                    *(float2*)cp = make_float2(vx, vy);
                }
            }
        }
    }
}

// ---------------- causal flash attention (fp32) -> bf16 hi/lo out -------------
__global__ __launch_bounds__(128) void attn_kernel(
    const float* __restrict__ q, const float* __restrict__ k,
    const float* __restrict__ v,
    __nv_bfloat16* __restrict__ oh, __nv_bfloat16* __restrict__ ol)
{
    __shared__ float ks[32][64];
    __shared__ float vs[32][64];
    __shared__ float ss[32][128];
    int tid = threadIdx.x;
    int bx = blockIdx.x;
    int hh = blockIdx.y;
    int bb = blockIdx.z;
    int qi = bx * 128 + tid;
    size_t base = ((size_t)bb * SEQ) * DMODEL + (size_t)hh * HEADD;

    float qr[64], o[64];
    const float* qrow = q + base + (size_t)qi * DMODEL;
    #pragma unroll
    for (int d4 = 0; d4 < 64; d4 += 4) {
        float4 t = *(const float4*)(qrow + d4);
        qr[d4+0] = t.x * 0.125f; qr[d4+1] = t.y * 0.125f;
        qr[d4+2] = t.z * 0.125f; qr[d4+3] = t.w * 0.125f;
        o[d4+0] = 0.f; o[d4+1] = 0.f; o[d4+2] = 0.f; o[d4+3] = 0.f;
    }
    float m = -1e30f, l = 0.f;

    int ntiles = bx * 4 + 4;
    for (int kt = 0; kt < ntiles; kt++) {
        const float* kb = k + base + (size_t)(kt * 32) * DMODEL;
        const float* vb = v + base + (size_t)(kt * 32) * DMODEL;
        #pragma unroll
        for (int it = 0; it < 4; it++) {
            int idx = tid + it * 128;
            int r = idx >> 4;
            int c = (idx & 15) << 2;
            *(float4*)&ks[r][c] = *(const float4*)(kb + (size_t)r * DMODEL + c);
            *(float4*)&vs[r][c] = *(const float4*)(vb + (size_t)r * DMODEL + c);
        }
        __syncthreads();
        int jmax = qi - kt * 32;
        if (jmax >= 0) {
            float tmax = -1e30f;
            for (int j = 0; j < 32; j++) {
                float acc = 0.f;
                #pragma unroll
                for (int d = 0; d < 64; d++) acc = fmaf(qr[d], ks[j][d], acc);
                if (j > jmax) acc = -1e30f;
                ss[j][tid] = acc;
                tmax = fmaxf(tmax, acc);
            }
            float mnew = fmaxf(m, tmax);
            float alpha = __expf(m - mnew);
            l *= alpha;
            #pragma unroll
            for (int d = 0; d < 64; d++) o[d] *= alpha;
            for (int j = 0; j < 32; j++) {
                float p = __expf(ss[j][tid] - mnew);
                l += p;
                #pragma unroll
                for (int d = 0; d < 64; d++) o[d] = fmaf(p, vs[j][d], o[d]);
            }
            m = mnew;
        }
        __syncthreads();
    }
    float inv = 1.0f / l;
    #pragma unroll
    for (int d4 = 0; d4 < 64; d4 += 4) {
        uint32_t h0, l0, h1, l1;
        split2(o[d4+0] * inv, o[d4+1] * inv, h0, l0);
        split2(o[d4+2] * inv, o[d4+3] * inv, h1, l1);
        size_t idx = (base + (size_t)qi * DMODEL + d4) >> 2;   // uint2 units
        ((uint2*)oh)[idx] = make_uint2(h0, h1);
        ((uint2*)ol)[idx] = make_uint2(l0, l1);
    }
}

// ---------------- host orchestration -----------------------------------------
static inline void tgemm(const __nv_bfloat16* Ah, const __nv_bfloat16* Al,
                         const __nv_bfloat16* Bh, const __nv_bfloat16* Bl,
                         const float* bias, float* C, int M, int N, int K,
                         int mode, __nv_bfloat16* oh = nullptr,
                         __nv_bfloat16* ol = nullptr) {
    dim3 grid(N / 128, M / 128);
    tgemm_kernel<<<grid, 256, GEMM_SMEM>>>(M, N, K, Ah, Al, Bh, Bl, bias, C,
                                           mode, oh, ol);
}
static inline void convw(const float* W, __nv_bfloat16* Th, __nv_bfloat16* Tl,
                         int K, int N) {
    convw_kernel<<<dim3(N / 32, K / 32), 256>>>(W, Th, Tl, K, N);
}

extern "C" void kernel_launch(void* const* d_in, const int* in_sizes, int n_in,
                              void* d_out, int out_size)
{
    const void*  x       = d_in[0];
    const float* tok_emb = (const float*)d_in[1];
    const float* pos_emb = (const float*)d_in[2];
    const float* Wq = (const float*)d_in[3];
    const float* bq = (const float*)d_in[4];
    const float* Wk = (const float*)d_in[5];
    const float* bk = (const float*)d_in[6];
    const float* Wv = (const float*)d_in[7];
    const float* bv = (const float*)d_in[8];
    const float* Wo = (const float*)d_in[9];
    const float* bo = (const float*)d_in[10];
    const float* ln1_g = (const float*)d_in[11];
    const float* ln1_b = (const float*)d_in[12];
    const float* ln2_g = (const float*)d_in[13];
    const float* ln2_b = (const float*)d_in[14];
    const float* W1 = (const float*)d_in[15];
    const float* b1 = (const float*)d_in[16];
    const float* W2 = (const float*)d_in[17];
    const float* b2 = (const float*)d_in[18];
    const float* lnf_g = (const float*)d_in[19];
    const float* lnf_b = (const float*)d_in[20];
    const float* Wout = (const float*)d_in[21];
    const float* bout = (const float*)d_in[22];

    float *h, *q, *k, *v;
    __nv_bfloat16 *xnh, *xnl, *atth, *attl, *ffh, *ffl, *wth, *wtl;
    cudaGetSymbolAddress((void**)&h,    g_h);
    cudaGetSymbolAddress((void**)&q,    g_q);
    cudaGetSymbolAddress((void**)&k,    g_k);
    cudaGetSymbolAddress((void**)&v,    g_v);
    cudaGetSymbolAddress((void**)&xnh,  g_xnh);
    cudaGetSymbolAddress((void**)&xnl,  g_xnl);
    cudaGetSymbolAddress((void**)&atth, g_atth);
    cudaGetSymbolAddress((void**)&attl, g_attl);
    cudaGetSymbolAddress((void**)&ffh,  g_ffh);
    cudaGetSymbolAddress((void**)&ffl,  g_ffl);
    cudaGetSymbolAddress((void**)&wth,  g_wth);
    cudaGetSymbolAddress((void**)&wtl,  g_wtl);

    cudaFuncSetAttribute(tgemm_kernel,
                         cudaFuncAttributeMaxDynamicSharedMemorySize, GEMM_SMEM);

    const int M = MROWS, D = DMODEL, F = FFDIM;

    detect_kernel<<<1, 256>>>((const int*)x, M);
    embed_kernel<<<M, 256>>>(x, tok_emb, pos_emb);

    // weight conversion (transpose + hi/lo split)
    for (int i = 0; i < NLAYER; i++) {
        size_t lb = (size_t)i * LW;
        convw(Wq + (size_t)i * DD, wth + lb + 0*DD, wtl + lb + 0*DD, D, D);
        convw(Wk + (size_t)i * DD, wth + lb + 1*DD, wtl + lb + 1*DD, D, D);
        convw(Wv + (size_t)i * DD, wth + lb + 2*DD, wtl + lb + 2*DD, D, D);
        convw(Wo + (size_t)i * DD, wth + lb + 3*DD, wtl + lb + 3*DD, D, D);
        convw(W1 + (size_t)i * D * F, wth + lb + 4*DD, wtl + lb + 4*DD, D, F);
        convw(W2 + (size_t)i * D * F, wth + lb + 4*DD + (size_t)D*F,
                                      wtl + lb + 4*DD + (size_t)D*F, F, D);
    }
    convw(Wout, wth + WOUT_OFF, wtl + WOUT_OFF, D, VOCAB);

    for (int i = 0; i < NLAYER; i++) {
        size_t lb = (size_t)i * LW;
        ln_kernel<<<M, 256>>>(h, ln1_g + (size_t)i * D, ln1_b + (size_t)i * D, xnh, xnl);
        tgemm(xnh, xnl, wth + lb + 0*DD, wtl + lb + 0*DD, bq + (size_t)i * D, q, M, D, D, 0);
        tgemm(xnh, xnl, wth + lb + 1*DD, wtl + lb + 1*DD, bk + (size_t)i * D, k, M, D, D, 0);
        tgemm(xnh, xnl, wth + lb + 2*DD, wtl + lb + 2*DD, bv + (size_t)i * D, v, M, D, D, 0);
        attn_kernel<<<dim3(SEQ / 128, NHEAD, BATCH), 128>>>(q, k, v, atth, attl);
        tgemm(atth, attl, wth + lb + 3*DD, wtl + lb + 3*DD, bo + (size_t)i * D, h, M, D, D, 2);
        ln_kernel<<<M, 256>>>(h, ln2_g + (size_t)i * D, ln2_b + (size_t)i * D, xnh, xnl);
        tgemm(xnh, xnl, wth + lb + 4*DD, wtl + lb + 4*DD, b1 + (size_t)i * F,
              nullptr, M, F, D, 1, ffh, ffl);
        tgemm(ffh, ffl, wth + lb + 4*DD + (size_t)D*F, wtl + lb + 4*DD + (size_t)D*F,
              b2 + (size_t)i * D, h, M, D, F, 2);
    }

    ln_kernel<<<M, 256>>>(h, lnf_g, lnf_b, xnh, xnl);
    tgemm(xnh, xnl, wth + WOUT_OFF, wtl + WOUT_OFF, bout, (float*)d_out, M, VOCAB, D, 0);
}

// round 9
// speedup vs baseline: 1.0418x; 1.0418x over previous
#include <cuda_runtime.h>
#include <cuda_bf16.h>
#include <math.h>
#include <stdint.h>

// Problem constants
#define BATCH 2
#define SEQ   1024
#define DMODEL 1024
#define NHEAD 16
#define HEADD 64
#define NLAYER 3
#define FFDIM 4096
#define VOCAB 32000
#define MROWS (BATCH*SEQ)   // 2048

// weight buffer layout (elems): per layer Wq,Wk,Wv,Wo (4x D*D), W1 (F*D), W2 (D*F)
#define DD (DMODEL*DMODEL)
#define LW (4*DD + 2*DMODEL*FFDIM)
#define WOUT_OFF (NLAYER*LW)
#define WTOT (WOUT_OFF + DMODEL*VOCAB)

// ---------------- scratch (device globals) -----------------------------------
__device__ float g_h  [MROWS*DMODEL];
__device__ float g_q  [MROWS*DMODEL];
__device__ float g_k  [MROWS*DMODEL];
__device__ float g_v  [MROWS*DMODEL];
__device__ __nv_bfloat16 g_xnh[MROWS*DMODEL];
__device__ __nv_bfloat16 g_xnl[MROWS*DMODEL];
__device__ __nv_bfloat16 g_atth[MROWS*DMODEL];
__device__ __nv_bfloat16 g_attl[MROWS*DMODEL];
__device__ __nv_bfloat16 g_ffh[MROWS*FFDIM];
__device__ __nv_bfloat16 g_ffl[MROWS*FFDIM];
__device__ __nv_bfloat16 g_wth[WTOT];
__device__ __nv_bfloat16 g_wtl[WTOT];
__device__ int   g_x_is64;

// ---------------- helpers -----------------------------------------------------
__device__ __forceinline__ uint32_t smem_u32(const void* p) {
    uint32_t a;
    asm("{ .reg .u64 t; cvta.to.shared.u64 t, %1; cvt.u32.u64 %0, t; }" : "=r"(a) : "l"(p));
    return a;
}
// hi = trunc-to-bf16 pair (packed), lo = rn-bf16(v - hi) pair (packed)
__device__ __forceinline__ void split2(float vx, float vy, uint32_t& hi, uint32_t& lo) {
    uint32_t ux = __float_as_uint(vx);
    uint32_t uy = __float_as_uint(vy);
    hi = __byte_perm(ux, uy, 0x7632);
    float lx = vx - __uint_as_float(ux & 0xFFFF0000u);
    float ly = vy - __uint_as_float(uy & 0xFFFF0000u);
    asm("cvt.rn.bf16x2.f32 %0, %1, %2;" : "=r"(lo) : "f"(ly), "f"(lx));
}
__device__ __forceinline__ void ldsm4(uint32_t* r, uint32_t addr) {
    asm volatile("ldmatrix.sync.aligned.m8n8.x4.shared.b16 {%0,%1,%2,%3}, [%4];"
                 : "=r"(r[0]), "=r"(r[1]), "=r"(r[2]), "=r"(r[3]) : "r"(addr));
}
__device__ __forceinline__ void mma16816(float* c, const uint32_t* a, const uint32_t* b) {
    asm volatile(
        "mma.sync.aligned.m16n8k16.row.col.f32.bf16.bf16.f32 "
        "{%0,%1,%2,%3}, {%4,%5,%6,%7}, {%8,%9}, {%0,%1,%2,%3};"
        : "+f"(c[0]), "+f"(c[1]), "+f"(c[2]), "+f"(c[3])
        : "r"(a[0]), "r"(a[1]), "r"(a[2]), "r"(a[3]), "r"(b[0]), "r"(b[1]));
}

// ---------------- token dtype detection --------------------------------------
__global__ void detect_kernel(const int* __restrict__ x32, int ntok) {
    __shared__ int ok;
    if (threadIdx.x == 0) ok = 1;
    __syncthreads();
    for (int i = threadIdx.x * 2 + 1; i < ntok; i += 2 * blockDim.x) {
        if (x32[i] != 0) { ok = 0; break; }
    }
    __syncthreads();
    if (threadIdx.x == 0) g_x_is64 = ok;
}

// ---------------- embedding ---------------------------------------------------
__global__ __launch_bounds__(256) void embed_kernel(
    const void* __restrict__ x,
    const float* __restrict__ tok_emb,
    const float* __restrict__ pos_emb)
{
    int row = blockIdx.x;
    int s = row & (SEQ - 1);
    long long t;
    if (g_x_is64) t = ((const long long*)x)[row];
    else          t = (long long)(((const int*)x)[row]);
    const float4* te = (const float4*)(tok_emb + (size_t)t * DMODEL);
    const float4* pe = (const float4*)(pos_emb + (size_t)s * DMODEL);
    float4* out = (float4*)(g_h + (size_t)row * DMODEL);
    int i = threadIdx.x;
    float4 a = te[i], b = pe[i];
    out[i] = make_float4(a.x + b.x, a.y + b.y, a.z + b.z, a.w + b.w);
}

// ---- weight transpose + split: W[K,N] -> Wt[N,K] bf16 hi/lo (vectorized) ----
// tile 32k x 32n; reads float4-coalesced; writes uint2 (4 bf16) per array.
__global__ __launch_bounds__(256) void convw_kernel(
    const float* __restrict__ W, __nv_bfloat16* __restrict__ Th,
    __nv_bfloat16* __restrict__ Tl, int K, int N)
{
    __shared__ float sm[32][33];
    int bk = blockIdx.y * 32, bn = blockIdx.x * 32;
    int t = threadIdx.x;
    int kr = t >> 3;            // 0..31 (k row)
    int c4 = (t & 7) * 4;       // 0..28 (n col, 4 wide)
    float4 v = *(const float4*)(W + (size_t)(bk + kr) * N + bn + c4);
    sm[kr][c4+0] = v.x; sm[kr][c4+1] = v.y; sm[kr][c4+2] = v.z; sm[kr][c4+3] = v.w;
    __syncthreads();
    int n  = t >> 3;            // 0..31 (out row = n)
    int k0 = (t & 7) * 4;       // 0..28 (k, 4 wide)
    float f0 = sm[k0+0][n], f1 = sm[k0+1][n], f2 = sm[k0+2][n], f3 = sm[k0+3][n];
    uint32_t h0, l0, h1, l1;
    split2(f0, f1, h0, l0);
    split2(f2, f3, h1, l1);
    size_t o = ((size_t)(bn + n) * K + bk + k0) >> 2;   // uint2 units (4 bf16)
    ((uint2*)Th)[o] = make_uint2(h0, h1);
    ((uint2*)Tl)[o] = make_uint2(l0, l1);
}

// ---------------- layernorm -> bf16 hi/lo -------------------------------------
__global__ __launch_bounds__(256) void ln_kernel(
    const float* __restrict__ x, const float* __restrict__ g,
    const float* __restrict__ b,
    __nv_bfloat16* __restrict__ yh, __nv_bfloat16* __restrict__ yl)
{
    int row = blockIdx.x;
    int tid = threadIdx.x;
    float4 val = ((const float4*)(x + (size_t)row * DMODEL))[tid];
    float s = val.x + val.y + val.z + val.w;
    float q = val.x*val.x + val.y*val.y + val.z*val.z + val.w*val.w;
    #pragma unroll
    for (int o = 16; o > 0; o >>= 1) {
        s += __shfl_xor_sync(0xffffffffu, s, o);
        q += __shfl_xor_sync(0xffffffffu, q, o);
    }
    __shared__ float sa[8], sb[8];
    __shared__ float s_mu, s_inv;
    int w = tid >> 5;
    if ((tid & 31) == 0) { sa[w] = s; sb[w] = q; }
    __syncthreads();
    if (tid == 0) {
        float ts = 0.f, tq = 0.f;
        #pragma unroll
        for (int i = 0; i < 8; i++) { ts += sa[i]; tq += sb[i]; }
        float mu = ts * (1.0f / DMODEL);
        float var = tq * (1.0f / DMODEL) - mu * mu;
        s_mu = mu;
        s_inv = rsqrtf(var + 1e-5f);
    }
    __syncthreads();
    float mu = s_mu, inv = s_inv;
    float4 gg = ((const float4*)g)[tid];
    float4 bb = ((const float4*)b)[tid];
    float ox = (val.x - mu) * inv * gg.x + bb.x;
    float oy = (val.y - mu) * inv * gg.y + bb.y;
    float oz = (val.z - mu) * inv * gg.z + bb.z;
    float ow = (val.w - mu) * inv * gg.w + bb.w;
    uint32_t h0, l0, h1, l1;
    split2(ox, oy, h0, l0);
    split2(oz, ow, h1, l1);
    ((uint2*)yh)[row * 256 + tid] = make_uint2(h0, h1);
    ((uint2*)yl)[row * 256 + tid] = make_uint2(l0, l1);
}

// ============================================================================
// bf16 split GEMM via mma.sync, R7-proven reg-prefetch mainloop:
//   C[M,N] = A @ W + bias ;  A:[M,K], W:[N,K] pre-split bf16 hi/lo
//   D = AhiBhi + AhiBlo + AloBhi
// Block 128x128, 8 warps (4m x 2n), warp tile 32x64, K-chunk 32, double-buffer.
// ============================================================================
#define ROWB      80
#define TILE_B    10240       // 128 rows * 80B
#define STAGE_B   40960       // Ahi Alo Bhi Blo
#define GEMM_SMEM (2*STAGE_B) // 81920

__global__ __launch_bounds__(256, 1) void tgemm_kernel(
    int M, int N, int K,
    const __nv_bfloat16* __restrict__ Ahi, const __nv_bfloat16* __restrict__ Alo,
    const __nv_bfloat16* __restrict__ Bhi, const __nv_bfloat16* __restrict__ Blo,
    const float* __restrict__ bias, float* C, int mode,
    __nv_bfloat16* outh, __nv_bfloat16* outl)
{
    extern __shared__ char smem[];
    uint32_t sb = smem_u32(smem);
    int tid = threadIdx.x;
    int wid = tid >> 5;
    int lane = tid & 31;
    int bm = blockIdx.y * 128;
    int bn = blockIdx.x * 128;

    float acc[2][8][4];
    #pragma unroll
    for (int i = 0; i < 2; i++)
        #pragma unroll
        for (int j = 0; j < 8; j++)
            #pragma unroll
            for (int q = 0; q < 4; q++) acc[i][j][q] = 0.f;

    const int KT = K >> 5;

    // ---- per-thread load coords ----
    // A: row am (0..127), uint4-pair index aq (0 or 2); chunk row = 4 uint4
    int am = tid >> 1;
    int aq = (tid & 1) * 2;
    const uint4* Ah4 = (const uint4*)(Ahi + (size_t)(bm + am) * K) + aq;
    const uint4* Al4 = (const uint4*)(Alo + (size_t)(bm + am) * K) + aq;
    // B: row bnn (0..127), uint4-pair index bq2
    int bnn = tid & 127;
    int bq2 = (tid >> 7) * 2;
    const uint4* Bh4 = (const uint4*)(Bhi + (size_t)(bn + bnn) * K) + bq2;
    const uint4* Bl4 = (const uint4*)(Blo + (size_t)(bn + bnn) * K) + bq2;

    uint4 rah0, rah1, ral0, ral1, rbh0, rbh1, rbl0, rbl1;
    char* st[2] = { smem, smem + STAGE_B };

#define LOAD_CHUNK(kt) do {                                                   \
        rah0 = Ah4[(kt)*4]; rah1 = Ah4[(kt)*4 + 1];                           \
        ral0 = Al4[(kt)*4]; ral1 = Al4[(kt)*4 + 1];                           \
        rbh0 = Bh4[(kt)*4]; rbh1 = Bh4[(kt)*4 + 1];                           \
        rbl0 = Bl4[(kt)*4]; rbl1 = Bl4[(kt)*4 + 1];                           \
    } while (0)

#define STORE_CHUNK(s) do {                                                   \
        char* pa = st[s] + am * ROWB + aq * 16;                               \
        *(uint4*)(pa)               = rah0;                                   \
        *(uint4*)(pa + 16)          = rah1;                                   \
        *(uint4*)(pa + TILE_B)      = ral0;                                   \
        *(uint4*)(pa + TILE_B + 16) = ral1;                                   \
        char* pb = st[s] + 2*TILE_B + bnn * ROWB + bq2 * 16;                  \
        *(uint4*)(pb)               = rbh0;                                   \
        *(uint4*)(pb + 16)          = rbh1;                                   \
        *(uint4*)(pb + TILE_B)      = rbl0;                                   \
        *(uint4*)(pb + TILE_B + 16) = rbl1;                                   \
    } while (0)

    // fragment lane addressing
    int wm = wid & 3;
    int wn = wid >> 2;
    int g  = lane >> 3;
    int lr = lane & 7;
    uint32_t a_off = (uint32_t)((wm * 32 + (g & 1) * 8 + lr) * ROWB + ((g >> 1) * 8) * 2);
    uint32_t b_off = (uint32_t)((wn * 64 + (g >> 1) * 8 + lr) * ROWB + ((g & 1) * 8) * 2);

    LOAD_CHUNK(0);
    STORE_CHUNK(0);
    __syncthreads();

    for (int kt = 0; kt < KT; kt++) {
        int s = kt & 1;
        if (kt + 1 < KT) LOAD_CHUNK(kt + 1);

        uint32_t sA = sb + s * STAGE_B + a_off;
        uint32_t sB = sb + s * STAGE_B + 2 * TILE_B + b_off;

        #pragma unroll
        for (int ks = 0; ks < 2; ks++) {
            uint32_t ah[2][4], al[2][4];
            uint32_t bh[8][2], bl[8][2];
            #pragma unroll
            for (int mt = 0; mt < 2; mt++) {
                uint32_t addr = sA + mt * 16 * ROWB + ks * 32;
                ldsm4(ah[mt], addr);
                ldsm4(al[mt], addr + TILE_B);
            }
            #pragma unroll
            for (int nt2 = 0; nt2 < 4; nt2++) {
                uint32_t addr = sB + nt2 * 16 * ROWB + ks * 32;
                uint32_t r[4];
                ldsm4(r, addr);
                bh[nt2*2][0] = r[0]; bh[nt2*2][1] = r[1];
                bh[nt2*2+1][0] = r[2]; bh[nt2*2+1][1] = r[3];
                ldsm4(r, addr + TILE_B);
                bl[nt2*2][0] = r[0]; bl[nt2*2][1] = r[1];
                bl[nt2*2+1][0] = r[2]; bl[nt2*2+1][1] = r[3];
            }
            #pragma unroll
            for (int mt = 0; mt < 2; mt++)
                #pragma unroll
                for (int nt = 0; nt < 8; nt++) {
                    mma16816(acc[mt][nt], ah[mt], bh[nt]);
                    mma16816(acc[mt][nt], ah[mt], bl[nt]);
                    mma16816(acc[mt][nt], al[mt], bh[nt]);
                }
        }

        if (kt + 1 < KT) {
            __syncthreads();
            STORE_CHUNK((kt + 1) & 1);
            __syncthreads();
        }
    }
#undef LOAD_CHUNK
#undef STORE_CHUNK

    // ---- epilogue ----
    int r0 = lane >> 2;
    int cc = (lane & 3) * 2;
    #pragma unroll
    for (int mt = 0; mt < 2; mt++) {
        int m0 = bm + wm * 32 + mt * 16 + r0;
        #pragma unroll
        for (int nt = 0; nt < 8; nt++) {
            int n0 = bn + wn * 64 + nt * 8 + cc;
            float b0 = bias[n0], b1 = bias[n0 + 1];
            #pragma unroll
            for (int half = 0; half < 2; half++) {
                int m = m0 + half * 8;
                float vx = acc[mt][nt][half*2 + 0] + b0;
                float vy = acc[mt][nt][half*2 + 1] + b1;
                if (mode == 1) {
                    vx = 0.5f * vx * (1.0f + erff(vx * 0.70710678118654752f));
                    vy = 0.5f * vy * (1.0f + erff(vy * 0.70710678118654752f));
                    uint32_t h, l;
                    split2(vx, vy, h, l);
                    *(uint32_t*)((char*)outh + ((size_t)m * N + n0) * 2) = h;
                    *(uint32_t*)((char*)outl + ((size_t)m * N + n0) * 2) = l;
                } else {
                    float* cp = C + (size_t)m * N + n0;
                    if (mode == 2) {
                        float2 old = *(float2*)cp;
                        vx += old.x; vy += old.y;
                    }
                    *(float2*)cp = make_float2(vx, vy);
                }
            }
        }
    }
}

// ---------------- causal flash attention (fp32) -> bf16 hi/lo out -------------
__global__ __launch_bounds__(128) void attn_kernel(
    const float* __restrict__ q, const float* __restrict__ k,
    const float* __restrict__ v,
    __nv_bfloat16* __restrict__ oh, __nv_bfloat16* __restrict__ ol)
{
    __shared__ float ks[32][64];
    __shared__ float vs[32][64];
    __shared__ float ss[32][128];
    int tid = threadIdx.x;
    int bx = blockIdx.x;
    int hh = blockIdx.y;
    int bb = blockIdx.z;
    int qi = bx * 128 + tid;
    size_t base = ((size_t)bb * SEQ) * DMODEL + (size_t)hh * HEADD;

    float qr[64], o[64];
    const float* qrow = q + base + (size_t)qi * DMODEL;
    #pragma unroll
    for (int d4 = 0; d4 < 64; d4 += 4) {
        float4 t = *(const float4*)(qrow + d4);
        qr[d4+0] = t.x * 0.125f; qr[d4+1] = t.y * 0.125f;
        qr[d4+2] = t.z * 0.125f; qr[d4+3] = t.w * 0.125f;
        o[d4+0] = 0.f; o[d4+1] = 0.f; o[d4+2] = 0.f; o[d4+3] = 0.f;
    }
    float m = -1e30f, l = 0.f;

    int ntiles = bx * 4 + 4;
    for (int kt = 0; kt < ntiles; kt++) {
        const float* kb = k + base + (size_t)(kt * 32) * DMODEL;
        const float* vb = v + base + (size_t)(kt * 32) * DMODEL;
        #pragma unroll
        for (int it = 0; it < 4; it++) {
            int idx = tid + it * 128;
            int r = idx >> 4;
            int c = (idx & 15) << 2;
            *(float4*)&ks[r][c] = *(const float4*)(kb + (size_t)r * DMODEL + c);
            *(float4*)&vs[r][c] = *(const float4*)(vb + (size_t)r * DMODEL + c);
        }
        __syncthreads();
        int jmax = qi - kt * 32;
        if (jmax >= 0) {
            float tmax = -1e30f;
            for (int j = 0; j < 32; j++) {
                float acc = 0.f;
                #pragma unroll
                for (int d = 0; d < 64; d++) acc = fmaf(qr[d], ks[j][d], acc);
                if (j > jmax) acc = -1e30f;
                ss[j][tid] = acc;
                tmax = fmaxf(tmax, acc);
            }
            float mnew = fmaxf(m, tmax);
            float alpha = __expf(m - mnew);
            l *= alpha;
            #pragma unroll
            for (int d = 0; d < 64; d++) o[d] *= alpha;
            for (int j = 0; j < 32; j++) {
                float p = __expf(ss[j][tid] - mnew);
                l += p;
                #pragma unroll
                for (int d = 0; d < 64; d++) o[d] = fmaf(p, vs[j][d], o[d]);
            }
            m = mnew;
        }
        __syncthreads();
    }
    float inv = 1.0f / l;
    #pragma unroll
    for (int d4 = 0; d4 < 64; d4 += 4) {
        uint32_t h0, l0, h1, l1;
        split2(o[d4+0] * inv, o[d4+1] * inv, h0, l0);
        split2(o[d4+2] * inv, o[d4+3] * inv, h1, l1);
        size_t idx = (base + (size_t)qi * DMODEL + d4) >> 2;
        ((uint2*)oh)[idx] = make_uint2(h0, h1);
        ((uint2*)ol)[idx] = make_uint2(l0, l1);
    }
}

// ---------------- host orchestration -----------------------------------------
static inline void tgemm(const __nv_bfloat16* Ah, const __nv_bfloat16* Al,
                         const __nv_bfloat16* Bh, const __nv_bfloat16* Bl,
                         const float* bias, float* C, int M, int N, int K,
                         int mode, __nv_bfloat16* oh = nullptr,
                         __nv_bfloat16* ol = nullptr) {
    dim3 grid(N / 128, M / 128);
    tgemm_kernel<<<grid, 256, GEMM_SMEM>>>(M, N, K, Ah, Al, Bh, Bl, bias, C,
                                           mode, oh, ol);
}
static inline void convw(const float* W, __nv_bfloat16* Th, __nv_bfloat16* Tl,
                         int K, int N) {
    convw_kernel<<<dim3(N / 32, K / 32), 256>>>(W, Th, Tl, K, N);
}

extern "C" void kernel_launch(void* const* d_in, const int* in_sizes, int n_in,
                              void* d_out, int out_size)
{
    const void*  x       = d_in[0];
    const float* tok_emb = (const float*)d_in[1];
    const float* pos_emb = (const float*)d_in[2];
    const float* Wq = (const float*)d_in[3];
    const float* bq = (const float*)d_in[4];
    const float* Wk = (const float*)d_in[5];
    const float* bk = (const float*)d_in[6];
    const float* Wv = (const float*)d_in[7];
    const float* bv = (const float*)d_in[8];
    const float* Wo = (const float*)d_in[9];
    const float* bo = (const float*)d_in[10];
    const float* ln1_g = (const float*)d_in[11];
    const float* ln1_b = (const float*)d_in[12];
    const float* ln2_g = (const float*)d_in[13];
    const float* ln2_b = (const float*)d_in[14];
    const float* W1 = (const float*)d_in[15];
    const float* b1 = (const float*)d_in[16];
    const float* W2 = (const float*)d_in[17];
    const float* b2 = (const float*)d_in[18];
    const float* lnf_g = (const float*)d_in[19];
    const float* lnf_b = (const float*)d_in[20];
    const float* Wout = (const float*)d_in[21];
    const float* bout = (const float*)d_in[22];

    float *h, *q, *k, *v;
    __nv_bfloat16 *xnh, *xnl, *atth, *attl, *ffh, *ffl, *wth, *wtl;
    cudaGetSymbolAddress((void**)&h,    g_h);
    cudaGetSymbolAddress((void**)&q,    g_q);
    cudaGetSymbolAddress((void**)&k,    g_k);
    cudaGetSymbolAddress((void**)&v,    g_v);
    cudaGetSymbolAddress((void**)&xnh,  g_xnh);
    cudaGetSymbolAddress((void**)&xnl,  g_xnl);
    cudaGetSymbolAddress((void**)&atth, g_atth);
    cudaGetSymbolAddress((void**)&attl, g_attl);
    cudaGetSymbolAddress((void**)&ffh,  g_ffh);
    cudaGetSymbolAddress((void**)&ffl,  g_ffl);
    cudaGetSymbolAddress((void**)&wth,  g_wth);
    cudaGetSymbolAddress((void**)&wtl,  g_wtl);

    cudaFuncSetAttribute(tgemm_kernel,
                         cudaFuncAttributeMaxDynamicSharedMemorySize, GEMM_SMEM);

    const int M = MROWS, D = DMODEL, F = FFDIM;

    detect_kernel<<<1, 256>>>((const int*)x, M);
    embed_kernel<<<M, 256>>>(x, tok_emb, pos_emb);

    // weight conversion (transpose + hi/lo split)
    for (int i = 0; i < NLAYER; i++) {
        size_t lb = (size_t)i * LW;
        convw(Wq + (size_t)i * DD, wth + lb + 0*DD, wtl + lb + 0*DD, D, D);
        convw(Wk + (size_t)i * DD, wth + lb + 1*DD, wtl + lb + 1*DD, D, D);
        convw(Wv + (size_t)i * DD, wth + lb + 2*DD, wtl + lb + 2*DD, D, D);
        convw(Wo + (size_t)i * DD, wth + lb + 3*DD, wtl + lb + 3*DD, D, D);
        convw(W1 + (size_t)i * D * F, wth + lb + 4*DD, wtl + lb + 4*DD, D, F);
        convw(W2 + (size_t)i * D * F, wth + lb + 4*DD + (size_t)D*F,
                                      wtl + lb + 4*DD + (size_t)D*F, F, D);
    }
    convw(Wout, wth + WOUT_OFF, wtl + WOUT_OFF, D, VOCAB);

    for (int i = 0; i < NLAYER; i++) {
        size_t lb = (size_t)i * LW;
        ln_kernel<<<M, 256>>>(h, ln1_g + (size_t)i * D, ln1_b + (size_t)i * D, xnh, xnl);
        tgemm(xnh, xnl, wth + lb + 0*DD, wtl + lb + 0*DD, bq + (size_t)i * D, q, M, D, D, 0);
        tgemm(xnh, xnl, wth + lb + 1*DD, wtl + lb + 1*DD, bk + (size_t)i * D, k, M, D, D, 0);
        tgemm(xnh, xnl, wth + lb + 2*DD, wtl + lb + 2*DD, bv + (size_t)i * D, v, M, D, D, 0);
        attn_kernel<<<dim3(SEQ / 128, NHEAD, BATCH), 128>>>(q, k, v, atth, attl);
        tgemm(atth, attl, wth + lb + 3*DD, wtl + lb + 3*DD, bo + (size_t)i * D, h, M, D, D, 2);
        ln_kernel<<<M, 256>>>(h, ln2_g + (size_t)i * D, ln2_b + (size_t)i * D, xnh, xnl);
        tgemm(xnh, xnl, wth + lb + 4*DD, wtl + lb + 4*DD, b1 + (size_t)i * F,
              nullptr, M, F, D, 1, ffh, ffl);
        tgemm(ffh, ffl, wth + lb + 4*DD + (size_t)D*F, wtl + lb + 4*DD + (size_t)D*F,
              b2 + (size_t)i * D, h, M, D, F, 2);
    }

    ln_kernel<<<M, 256>>>(h, lnf_g, lnf_b, xnh, xnl);
    tgemm(xnh, xnl, wth + WOUT_OFF, wtl + WOUT_OFF, bout, (float*)d_out, M, VOCAB, D, 0);
}